// round 3
// baseline (speedup 1.0000x reference)
#include <cuda_runtime.h>
#include <cuda_fp16.h>
#include <cstdint>

// ---------------- problem dims ----------------
constexpr int B_   = 32;
constexpr int CIN  = 256;
constexpr int COUT = 256;
constexpr int HW   = 1024;   // 32x32
constexpr int TDIM = 256;
constexpr int HID  = 64;
constexpr int E_   = 4;
constexpr int TAPS = 9;

// ---------------- device scratch (static: allocation rules) ----------------
__device__ __align__(16) __half g_xh[(size_t)B_ * CIN * HW];              // x in fp16
__device__ float  g_pooled[B_ * CIN];
__device__ float  g_rw[B_ * E_];
__device__ __align__(16) __half g_weff[(size_t)B_ * TAPS * COUT * CIN];   // [b][tap][cout][cin]

// ---------------- helpers ----------------
#define SW128(off)  ((off) ^ (((off) >> 3) & 0x70))   // 128B-row swizzle
#define SW256(off)  ((off) ^ (((off) >> 4) & 0x70))   // 256B-row swizzle

__device__ __forceinline__ uint32_t smem_u32(const void* p) {
    uint32_t a;
    asm("{ .reg .u64 t; cvta.to.shared.u64 t, %1; cvt.u32.u64 %0, t; }"
        : "=r"(a) : "l"(p));
    return a;
}

__device__ __forceinline__ void ldsm_x4(uint32_t* r, uint32_t addr) {
    asm volatile("ldmatrix.sync.aligned.m8n8.x4.shared.b16 {%0,%1,%2,%3}, [%4];"
                 : "=r"(r[0]), "=r"(r[1]), "=r"(r[2]), "=r"(r[3]) : "r"(addr));
}
__device__ __forceinline__ void ldsm_x4_t(uint32_t* r, uint32_t addr) {
    asm volatile("ldmatrix.sync.aligned.m8n8.x4.trans.shared.b16 {%0,%1,%2,%3}, [%4];"
                 : "=r"(r[0]), "=r"(r[1]), "=r"(r[2]), "=r"(r[3]) : "r"(addr));
}
__device__ __forceinline__ void mma16816(float* c, const uint32_t* a,
                                         uint32_t b0, uint32_t b1) {
    asm volatile(
        "mma.sync.aligned.m16n8k16.row.col.f32.f16.f16.f32 "
        "{%0,%1,%2,%3}, {%4,%5,%6,%7}, {%8,%9}, {%0,%1,%2,%3};"
        : "+f"(c[0]), "+f"(c[1]), "+f"(c[2]), "+f"(c[3])
        : "r"(a[0]), "r"(a[1]), "r"(a[2]), "r"(a[3]), "r"(b0), "r"(b1));
}

// ---------------- kernel 1: pool (mean over HW) + fp32->fp16 convert ----------------
__global__ __launch_bounds__(256) void pool_convert_kernel(const float* __restrict__ x) {
    int wid = threadIdx.x >> 5, lid = threadIdx.x & 31;
    int rc = blockIdx.x * 8 + wid;               // 0 .. B_*CIN-1
    const float4* xp = reinterpret_cast<const float4*>(x + (size_t)rc * HW);
    uint2* op = reinterpret_cast<uint2*>(g_xh + (size_t)rc * HW);
    float s = 0.f;
    #pragma unroll
    for (int i = 0; i < 8; i++) {
        float4 v = xp[lid + i * 32];
        s += (v.x + v.y) + (v.z + v.w);
        __half2 h0 = __floats2half2_rn(v.x, v.y);
        __half2 h1 = __floats2half2_rn(v.z, v.w);
        uint2 u;
        u.x = *reinterpret_cast<uint32_t*>(&h0);
        u.y = *reinterpret_cast<uint32_t*>(&h1);
        op[lid + i * 32] = u;
    }
    #pragma unroll
    for (int o = 16; o > 0; o >>= 1) s += __shfl_xor_sync(0xFFFFFFFFu, s, o);
    if (lid == 0) g_pooled[rc] = s * (1.f / 1024.f);
}

// ---------------- kernel 2: router MLP + softmax -> g_rw ----------------
__global__ __launch_bounds__(HID) void router_kernel(
    const float* __restrict__ te,
    const float* __restrict__ Wq, const float* __restrict__ bq,
    const float* __restrict__ Wk, const float* __restrict__ bk,
    const float* __restrict__ Wv, const float* __restrict__ bv,
    const float* __restrict__ Wm1, const float* __restrict__ bm1,
    const float* __restrict__ Wm2, const float* __restrict__ bm2,
    const float* __restrict__ Wc, const float* __restrict__ bc) {
    int b = blockIdx.x, j = threadIdx.x;
    __shared__ float s_in[TDIM], s_p[CIN], s_xa[HID], s_h[HID], s_xm[HID], s_l[E_];
    for (int i = j; i < TDIM; i += HID) s_in[i] = te[b * TDIM + i];
    for (int i = j; i < CIN; i += HID) s_p[i] = g_pooled[b * CIN + i];
    __syncthreads();

    float q = bq[j], k = bk[j], v = bv[j];
    for (int i = 0; i < TDIM; i++) q += Wq[j * TDIM + i] * s_in[i];
    for (int i = 0; i < CIN; i++) {
        float p = s_p[i];
        k += Wk[j * CIN + i] * p;
        v += Wv[j * CIN + i] * p;
    }
    float attn = 1.f / (1.f + expf(-(q * k)));
    float xa = v * attn;
    s_xa[j] = xa;
    __syncthreads();

    float h = bm1[j];
    for (int i = 0; i < HID; i++) h += Wm1[j * HID + i] * s_xa[i];
    h = h / (1.f + expf(-h));         // silu
    s_h[j] = h;
    __syncthreads();

    float xm = xa + bm2[j];
    for (int i = 0; i < HID; i++) xm += Wm2[j * HID + i] * s_h[i];
    s_xm[j] = xm;
    __syncthreads();

    if (j < E_) {
        float l = bc[j];
        for (int i = 0; i < HID; i++) l += Wc[j * HID + i] * s_xm[i];
        s_l[j] = l;
    }
    __syncthreads();
    if (j == 0) {
        float mx = s_l[0];
        for (int e = 1; e < E_; e++) mx = fmaxf(mx, s_l[e]);
        float sm = 0.f, ex[E_];
        for (int e = 0; e < E_; e++) { ex[e] = expf(s_l[e] - mx); sm += ex[e]; }
        float inv = 1.f / sm;
        for (int e = 0; e < E_; e++) g_rw[b * E_ + e] = ex[e] * inv;
    }
}

// ---------------- kernel 3: mix expert weights -> g_weff [b][tap][cout][cin] fp16 ----------------
__global__ __launch_bounds__(256) void mix_kernel(const float* __restrict__ weight) {
    int o = blockIdx.x, c = threadIdx.x;
    __shared__ float ws[E_ * CIN * TAPS];   // 36 KB: weight[:, o, :, :]
    __shared__ float srw[B_ * E_];
    for (int e = 0; e < E_; e++) {
        const float* src = weight + (size_t)(e * COUT + o) * (CIN * TAPS);
        for (int i = c; i < CIN * TAPS; i += 256) ws[e * CIN * TAPS + i] = src[i];
    }
    for (int i = c; i < B_ * E_; i += 256) srw[i] = g_rw[i];
    __syncthreads();

    float wv[E_][TAPS];
    #pragma unroll
    for (int e = 0; e < E_; e++)
        #pragma unroll
        for (int t = 0; t < TAPS; t++) wv[e][t] = ws[e * CIN * TAPS + c * TAPS + t];

    for (int b = 0; b < B_; b++) {
        float r0 = srw[b * 4 + 0], r1 = srw[b * 4 + 1];
        float r2 = srw[b * 4 + 2], r3 = srw[b * 4 + 3];
        #pragma unroll
        for (int t = 0; t < TAPS; t++) {
            float v = r0 * wv[0][t] + r1 * wv[1][t] + r2 * wv[2][t] + r3 * wv[3][t];
            g_weff[(((size_t)b * TAPS + t) * COUT + o) * CIN + c] = __float2half_rn(v);
        }
    }
}

// ---------------- kernel 4: batched implicit-GEMM conv via mma.sync (HMMA) ----------------
// CTA: b = blockIdx.z, mt = blockIdx.y (128 couts), nt = blockIdx.x (128 pixels = 4 rows)
// 8 warps, warp tile 32(m) x 64(n). K loop: 9 taps x 4 cin-chunks of 64.
__global__ __launch_bounds__(256) void conv_kernel(float* __restrict__ out) {
    __shared__ __align__(1024) __half sA[128 * 64];   // [m][k]  128B rows, SW128
    __shared__ __align__(1024) __half sB[64 * 128];   // [k][n]  256B rows, SW256

    const int tid = threadIdx.x, lid = tid & 31, wid = tid >> 5;
    const int nt = blockIdx.x, mt = blockIdx.y, b = blockIdx.z;
    const int wm = wid & 3, wn = wid >> 2;
    const int h0 = nt * 4;

    const uint32_t sa = smem_u32(sA);
    const uint32_t sbm = smem_u32(sB);
    const __half* __restrict__ xb = g_xh + (size_t)b * CIN * HW;

    float acc[2][8][4];
    #pragma unroll
    for (int mi = 0; mi < 2; mi++)
        #pragma unroll
        for (int ni = 0; ni < 8; ni++)
            #pragma unroll
            for (int q = 0; q < 4; q++) acc[mi][ni][q] = 0.f;

    // B-fill thread mapping: each thread owns one (k-row, 32-pixel row)
    const int kk = tid >> 2;        // 0..63  (cin within chunk)
    const int r  = tid & 3;         // 0..3   (image row within tile)

    #pragma unroll
    for (int tap = 0; tap < TAPS; tap++) {
        const int dh = tap / 3 - 1;
        const int dw = tap % 3 - 1;
        const int h  = h0 + r + dh;
        const bool hok = (unsigned)h < 32u;

        #pragma unroll 1
        for (int cc = 0; cc < 4; cc++) {
            // ---- A tile: w_eff[b][tap][mt*128 + m][cc*64 + k] ----
            const __half* asrc =
                g_weff + (((size_t)b * TAPS + tap) * COUT + mt * 128) * CIN + cc * 64;
            #pragma unroll
            for (int i = 0; i < 4; i++) {
                int idx = i * 256 + tid;          // 0..1023
                int m = idx >> 3, j = idx & 7;
                uint4 v = *reinterpret_cast<const uint4*>(asrc + m * CIN + j * 8);
                uint32_t off = (uint32_t)(m * 128 + j * 16);
                *reinterpret_cast<uint4*>((char*)sA + SW128(off)) = v;
            }
            // ---- B tile (im2col, [k][n]): B[kk][r*32+w] = x[cc*64+kk][h][w+dw] ----
            {
                ushort v[32];
                if (hok) {
                    const __half* xr = xb + ((size_t)(cc * 64 + kk)) * HW + h * 32;
                    #pragma unroll
                    for (int j = 0; j < 4; j++) {
                        uint4 t = *reinterpret_cast<const uint4*>(xr + j * 8);
                        const ushort* p = reinterpret_cast<const ushort*>(&t);
                        #pragma unroll
                        for (int q = 0; q < 8; q++) v[j * 8 + q] = p[q];
                    }
                } else {
                    #pragma unroll
                    for (int n = 0; n < 32; n++) v[n] = 0;
                }
                #pragma unroll
                for (int j = 0; j < 4; j++) {
                    uint4 ov;
                    uint32_t* po = reinterpret_cast<uint32_t*>(&ov);
                    #pragma unroll
                    for (int q = 0; q < 4; q++) {
                        int n0i = j * 8 + q * 2, n1i = n0i + 1;
                        int w0 = n0i + dw, w1 = n1i + dw;
                        uint32_t lo = (w0 >= 0 && w0 < 32) ? (uint32_t)v[w0] : 0u;
                        uint32_t hi = (w1 >= 0 && w1 < 32) ? (uint32_t)v[w1] : 0u;
                        po[q] = lo | (hi << 16);
                    }
                    uint32_t off = (uint32_t)(kk * 256 + (r * 32 + j * 8) * 2);
                    *reinterpret_cast<uint4*>((char*)sB + SW256(off)) = ov;
                }
            }
            __syncthreads();

            // ---- 4 k-steps of 16 ----
            #pragma unroll
            for (int ks = 0; ks < 4; ks++) {
                uint32_t afr[2][4];
                #pragma unroll
                for (int mi = 0; mi < 2; mi++) {
                    int row = wm * 32 + mi * 16 + (lid & 15);
                    uint32_t off = (uint32_t)(row * 128 + ks * 32 + (lid >> 4) * 16);
                    ldsm_x4(afr[mi], sa + SW128(off));
                }
                uint32_t bfr[4][4];
                #pragma unroll
                for (int nb = 0; nb < 4; nb++) {
                    int krow = ks * 16 + (lid & 7) + ((lid >> 3) & 1) * 8;
                    int ncol = wn * 64 + nb * 16 + (lid >> 4) * 8;
                    uint32_t off = (uint32_t)(krow * 256 + ncol * 2);
                    ldsm_x4_t(bfr[nb], sbm + SW256(off));
                }
                #pragma unroll
                for (int mi = 0; mi < 2; mi++)
                    #pragma unroll
                    for (int ni = 0; ni < 8; ni++) {
                        const uint32_t* bp = &bfr[ni >> 1][(ni & 1) * 2];
                        mma16816(acc[mi][ni], afr[mi], bp[0], bp[1]);
                    }
            }
            __syncthreads();
        }
    }

    // ---- epilogue: accum regs -> out ----
    #pragma unroll
    for (int mi = 0; mi < 2; mi++) {
        #pragma unroll
        for (int ni = 0; ni < 8; ni++) {
            int row = mt * 128 + wm * 32 + mi * 16 + (lid >> 2);
            int col = nt * 128 + wn * 64 + ni * 8 + (lid & 3) * 2;
            float* op0 = out + ((size_t)b * COUT + row) * HW + col;
            float* op1 = op0 + 8 * HW;   // row + 8
            *reinterpret_cast<float2*>(op0) = make_float2(acc[mi][ni][0], acc[mi][ni][1]);
            *reinterpret_cast<float2*>(op1) = make_float2(acc[mi][ni][2], acc[mi][ni][3]);
        }
    }
}

// ---------------- launcher ----------------
extern "C" void kernel_launch(void* const* d_in, const int* in_sizes, int n_in,
                              void* d_out, int out_size) {
    const float* x      = (const float*)d_in[0];
    const float* te     = (const float*)d_in[1];
    const float* weight = (const float*)d_in[2];
    const float* Wq = (const float*)d_in[3],  *bq = (const float*)d_in[4];
    const float* Wk = (const float*)d_in[5],  *bk = (const float*)d_in[6];
    const float* Wv = (const float*)d_in[7],  *bv = (const float*)d_in[8];
    const float* Wm1 = (const float*)d_in[9],  *bm1 = (const float*)d_in[10];
    const float* Wm2 = (const float*)d_in[11], *bm2 = (const float*)d_in[12];
    const float* Wc  = (const float*)d_in[13], *bc  = (const float*)d_in[14];
    float* out = (float*)d_out;

    pool_convert_kernel<<<(B_ * CIN) / 8, 256>>>(x);
    router_kernel<<<B_, HID>>>(te, Wq, bq, Wk, bk, Wv, bv, Wm1, bm1, Wm2, bm2, Wc, bc);
    mix_kernel<<<COUT, 256>>>(weight);
    conv_kernel<<<dim3(8, 2, B_), 256>>>(out);
}

// round 4
// speedup vs baseline: 1.6076x; 1.6076x over previous
#include <cuda_runtime.h>
#include <cuda_fp16.h>
#include <cstdint>

// ---------------- problem dims ----------------
constexpr int B_   = 32;
constexpr int CIN  = 256;
constexpr int COUT = 256;
constexpr int HW   = 1024;   // 32x32
constexpr int TDIM = 256;
constexpr int HID  = 64;
constexpr int E_   = 4;
constexpr int TAPS = 9;

// ---------------- device scratch (static: allocation rules) ----------------
__device__ __align__(16) __half g_xh[(size_t)B_ * CIN * HW];              // x in fp16
__device__ float  g_pooled[B_ * CIN];
__device__ float  g_rw[B_ * E_];
__device__ __align__(16) __half g_weff[(size_t)B_ * TAPS * COUT * CIN];   // [b][tap][cout][cin]

// ---------------- helpers ----------------
#define SW128(off)  ((off) ^ (((off) >> 3) & 0x70))   // 128B-row swizzle

__device__ __forceinline__ uint32_t smem_u32(const void* p) {
    uint32_t a;
    asm("{ .reg .u64 t; cvta.to.shared.u64 t, %1; cvt.u32.u64 %0, t; }"
        : "=r"(a) : "l"(p));
    return a;
}
__device__ __forceinline__ void ldsm_x4(uint32_t* r, uint32_t addr) {
    asm volatile("ldmatrix.sync.aligned.m8n8.x4.shared.b16 {%0,%1,%2,%3}, [%4];"
                 : "=r"(r[0]), "=r"(r[1]), "=r"(r[2]), "=r"(r[3]) : "r"(addr));
}
__device__ __forceinline__ void mma16816(float* c, const uint32_t* a,
                                         uint32_t b0, uint32_t b1) {
    asm volatile(
        "mma.sync.aligned.m16n8k16.row.col.f32.f16.f16.f32 "
        "{%0,%1,%2,%3}, {%4,%5,%6,%7}, {%8,%9}, {%0,%1,%2,%3};"
        : "+f"(c[0]), "+f"(c[1]), "+f"(c[2]), "+f"(c[3])
        : "r"(a[0]), "r"(a[1]), "r"(a[2]), "r"(a[3]), "r"(b0), "r"(b1));
}
__device__ __forceinline__ void cp_async16(uint32_t dst, const void* src) {
    asm volatile("cp.async.cg.shared.global [%0], [%1], 16;" :: "r"(dst), "l"(src));
}
#define CP_COMMIT() asm volatile("cp.async.commit_group;" ::: "memory")
#define CP_WAIT(N)  asm volatile("cp.async.wait_group %0;" :: "n"(N) : "memory")
__device__ __forceinline__ uint32_t ldshared_b32(uint32_t addr) {
    uint32_t v;
    asm volatile("ld.shared.b32 %0, [%1];" : "=r"(v) : "r"(addr));
    return v;
}

// ---------------- kernel 1: pool (mean over HW) + fp32->fp16 convert ----------------
__global__ __launch_bounds__(256) void pool_convert_kernel(const float* __restrict__ x) {
    int wid = threadIdx.x >> 5, lid = threadIdx.x & 31;
    int rc = blockIdx.x * 8 + wid;               // 0 .. B_*CIN-1
    const float4* xp = reinterpret_cast<const float4*>(x + (size_t)rc * HW);
    uint2* op = reinterpret_cast<uint2*>(g_xh + (size_t)rc * HW);
    float s = 0.f;
    #pragma unroll
    for (int i = 0; i < 8; i++) {
        float4 v = xp[lid + i * 32];
        s += (v.x + v.y) + (v.z + v.w);
        __half2 h0 = __floats2half2_rn(v.x, v.y);
        __half2 h1 = __floats2half2_rn(v.z, v.w);
        uint2 u;
        u.x = *reinterpret_cast<uint32_t*>(&h0);
        u.y = *reinterpret_cast<uint32_t*>(&h1);
        op[lid + i * 32] = u;
    }
    #pragma unroll
    for (int o = 16; o > 0; o >>= 1) s += __shfl_xor_sync(0xFFFFFFFFu, s, o);
    if (lid == 0) g_pooled[rc] = s * (1.f / 1024.f);
}

// ---------------- kernel 2: router MLP + softmax -> g_rw ----------------
__global__ __launch_bounds__(HID) void router_kernel(
    const float* __restrict__ te,
    const float* __restrict__ Wq, const float* __restrict__ bq,
    const float* __restrict__ Wk, const float* __restrict__ bk,
    const float* __restrict__ Wv, const float* __restrict__ bv,
    const float* __restrict__ Wm1, const float* __restrict__ bm1,
    const float* __restrict__ Wm2, const float* __restrict__ bm2,
    const float* __restrict__ Wc, const float* __restrict__ bc) {
    int b = blockIdx.x, j = threadIdx.x;
    __shared__ float s_in[TDIM], s_p[CIN], s_xa[HID], s_h[HID], s_xm[HID], s_l[E_];
    for (int i = j; i < TDIM; i += HID) s_in[i] = te[b * TDIM + i];
    for (int i = j; i < CIN; i += HID) s_p[i] = g_pooled[b * CIN + i];
    __syncthreads();

    float q = bq[j], k = bk[j], v = bv[j];
    for (int i = 0; i < TDIM; i++) q += Wq[j * TDIM + i] * s_in[i];
    for (int i = 0; i < CIN; i++) {
        float p = s_p[i];
        k += Wk[j * CIN + i] * p;
        v += Wv[j * CIN + i] * p;
    }
    float attn = 1.f / (1.f + expf(-(q * k)));
    float xa = v * attn;
    s_xa[j] = xa;
    __syncthreads();

    float h = bm1[j];
    for (int i = 0; i < HID; i++) h += Wm1[j * HID + i] * s_xa[i];
    h = h / (1.f + expf(-h));         // silu
    s_h[j] = h;
    __syncthreads();

    float xm = xa + bm2[j];
    for (int i = 0; i < HID; i++) xm += Wm2[j * HID + i] * s_h[i];
    s_xm[j] = xm;
    __syncthreads();

    if (j < E_) {
        float l = bc[j];
        for (int i = 0; i < HID; i++) l += Wc[j * HID + i] * s_xm[i];
        s_l[j] = l;
    }
    __syncthreads();
    if (j == 0) {
        float mx = s_l[0];
        for (int e = 1; e < E_; e++) mx = fmaxf(mx, s_l[e]);
        float sm = 0.f, ex[E_];
        for (int e = 0; e < E_; e++) { ex[e] = expf(s_l[e] - mx); sm += ex[e]; }
        float inv = 1.f / sm;
        for (int e = 0; e < E_; e++) g_rw[b * E_ + e] = ex[e] * inv;
    }
}

// ---------------- kernel 3: mix expert weights -> g_weff [b][tap][cout][cin] fp16 ----------------
__global__ __launch_bounds__(256) void mix_kernel(const float* __restrict__ weight) {
    int o = blockIdx.x, c = threadIdx.x;
    __shared__ float ws[E_ * CIN * TAPS];   // 36 KB: weight[:, o, :, :]
    __shared__ float srw[B_ * E_];
    for (int e = 0; e < E_; e++) {
        const float* src = weight + (size_t)(e * COUT + o) * (CIN * TAPS);
        for (int i = c; i < CIN * TAPS; i += 256) ws[e * CIN * TAPS + i] = src[i];
    }
    for (int i = c; i < B_ * E_; i += 256) srw[i] = g_rw[i];
    __syncthreads();

    float wv[E_][TAPS];
    #pragma unroll
    for (int e = 0; e < E_; e++)
        #pragma unroll
        for (int t = 0; t < TAPS; t++) wv[e][t] = ws[e * CIN * TAPS + c * TAPS + t];

    for (int b = 0; b < B_; b++) {
        float r0 = srw[b * 4 + 0], r1 = srw[b * 4 + 1];
        float r2 = srw[b * 4 + 2], r3 = srw[b * 4 + 3];
        #pragma unroll
        for (int t = 0; t < TAPS; t++) {
            float v = r0 * wv[0][t] + r1 * wv[1][t] + r2 * wv[2][t] + r3 * wv[3][t];
            g_weff[(((size_t)b * TAPS + t) * COUT + o) * CIN + c] = __float2half_rn(v);
        }
    }
}

// ---------------- kernel 4: batched implicit-GEMM conv via mma.sync (HMMA) ----------------
// CTA: b = blockIdx.z, mt = blockIdx.y (128 couts), nt = blockIdx.x (128 pixels = 4 rows)
// cc-chunk outer (x neighborhood loaded ONCE per chunk, reused by all 9 taps via
// shifted addressing), tap inner. A double-buffered via cp.async.
constexpr int PIXB = 144;                 // bytes per pixel in sX (64 cin + 8 pad halves)
constexpr int ROWB = 34 * PIXB;           // 4896 B per image row (halo cols 0 and 33)
constexpr int SX_BYTES = 6 * ROWB;        // 29376
constexpr int SA_OFF   = 30720;           // 1024-aligned
constexpr int SA_BYTES = 128 * 128;       // 16 KB per A buffer
constexpr int CONV_SMEM = SA_OFF + 2 * SA_BYTES;   // 63488

__global__ __launch_bounds__(256, 2) void conv_kernel(float* __restrict__ out) {
    extern __shared__ char smem[];
    char* sx = smem;
    const uint32_t sxa = smem_u32(sx);
    const uint32_t saa[2] = { sxa + SA_OFF, sxa + SA_OFF + SA_BYTES };

    const int tid = threadIdx.x, lid = tid & 31, wid = tid >> 5;
    const int nt = blockIdx.x, mt = blockIdx.y, b = blockIdx.z;
    const int wm = wid & 3, wn = wid >> 2;
    const int h0 = nt * 4;

    const __half* __restrict__ xb = g_xh + (size_t)b * CIN * HW;
    const __half* __restrict__ wbase =
        g_weff + ((size_t)b * TAPS * COUT + (size_t)mt * 128) * CIN;

    float acc[2][8][4];
    #pragma unroll
    for (int mi = 0; mi < 2; mi++)
        #pragma unroll
        for (int ni = 0; ni < 8; ni++)
            #pragma unroll
            for (int q = 0; q < 4; q++) acc[mi][ni][q] = 0.f;

    // per-thread base addresses of B-fragment pixels (no tap shift, kstep 0)
    uint32_t bp[8];
    #pragma unroll
    for (int nb = 0; nb < 8; nb++) {
        int n = wn * 64 + nb * 8 + (lid >> 2);
        int r = n >> 5, w = n & 31;
        bp[nb] = sxa + (uint32_t)(((r + 1) * 34 + (w + 1)) * PIXB + (lid & 3) * 4);
    }

    // A cp.async fill indices
    const int am = tid >> 1;                 // wait no — 1024 vectors over 256 threads, 4 each
    (void)am;

    // prologue: prefetch A(tap=0, cc=0)
    {
        const __half* asrc = wbase;          // tap 0, cc 0
        #pragma unroll
        for (int i = 0; i < 4; i++) {
            int idx = i * 256 + tid;
            int m = idx >> 3, j = idx & 7;
            cp_async16(saa[0] + SW128((uint32_t)(m * 128 + j * 16)), asrc + m * CIN + j * 8);
        }
        CP_COMMIT();
    }

    const int kfill = tid >> 2;              // cin within chunk for sX fill
    const int wg    = tid & 3;               // 8-pixel group within image row

    #pragma unroll 1
    for (int cc = 0; cc < 4; cc++) {
        // ---- fill sX for this chunk: raw x neighborhood, zero halo ----
        // halo cols 0 and 33 (threads 0..95)
        if (tid < 96) {
            int rr = tid / 16, sub = tid % 16;
            int col = (sub >> 3) ? 33 : 0, kq = sub & 7;
            *reinterpret_cast<uint4*>(sx + rr * ROWB + col * PIXB + kq * 16) =
                make_uint4(0u, 0u, 0u, 0u);
        }
        #pragma unroll
        for (int rr = 0; rr < 6; rr++) {
            int h = h0 + rr - 1;
            uint4 v = make_uint4(0u, 0u, 0u, 0u);
            if ((unsigned)h < 32u)
                v = *reinterpret_cast<const uint4*>(xb + (size_t)(cc * 64 + kfill) * HW +
                                                    h * 32 + wg * 8);
            const ushort* p = reinterpret_cast<const ushort*>(&v);
            char* base = sx + rr * ROWB + (1 + wg * 8) * PIXB + kfill * 2;
            #pragma unroll
            for (int q = 0; q < 8; q++)
                *reinterpret_cast<ushort*>(base + q * PIXB) = p[q];
        }

        #pragma unroll
        for (int tap = 0; tap < TAPS; tap++) {
            const int s = cc * TAPS + tap;
            const bool last = (s == 35);
            // prefetch next A tile into the other buffer
            if (!last) {
                const int ntap = (tap == 8) ? 0 : tap + 1;
                const int ncc  = (tap == 8) ? cc + 1 : cc;
                const __half* asrc = wbase + (size_t)ntap * COUT * CIN + ncc * 64;
                const uint32_t dst = saa[(s + 1) & 1];
                #pragma unroll
                for (int i = 0; i < 4; i++) {
                    int idx = i * 256 + tid;
                    int m = idx >> 3, j = idx & 7;
                    cp_async16(dst + SW128((uint32_t)(m * 128 + j * 16)),
                               asrc + m * CIN + j * 8);
                }
                CP_COMMIT();
                CP_WAIT(1);
            } else {
                CP_WAIT(0);
            }
            __syncthreads();   // A(s) visible + sX fill complete (tap 0)

            const uint32_t sa = saa[s & 1];
            const int dh = tap / 3 - 1, dw = tap % 3 - 1;
            const int delta = (dh * 34 + dw) * PIXB;

            #pragma unroll
            for (int ks = 0; ks < 4; ks++) {
                uint32_t afr[2][4];
                #pragma unroll
                for (int mi = 0; mi < 2; mi++) {
                    int row = wm * 32 + mi * 16 + (lid & 15);
                    uint32_t off = (uint32_t)(row * 128 + ks * 32 + (lid >> 4) * 16);
                    ldsm_x4(afr[mi], sa + SW128(off));
                }
                #pragma unroll
                for (int nb = 0; nb < 8; nb++) {
                    uint32_t a0 = bp[nb] + (uint32_t)(delta + ks * 32);
                    uint32_t b0 = ldshared_b32(a0);
                    uint32_t b1 = ldshared_b32(a0 + 16);
                    mma16816(acc[0][nb], afr[0], b0, b1);
                    mma16816(acc[1][nb], afr[1], b0, b1);
                }
            }
            __syncthreads();   // all warps done reading buffers before next overwrite
        }
    }

    // ---- epilogue: accum regs -> out ----
    #pragma unroll
    for (int mi = 0; mi < 2; mi++) {
        #pragma unroll
        for (int ni = 0; ni < 8; ni++) {
            int row = mt * 128 + wm * 32 + mi * 16 + (lid >> 2);
            int col = nt * 128 + wn * 64 + ni * 8 + (lid & 3) * 2;
            float* op0 = out + ((size_t)b * COUT + row) * HW + col;
            float* op1 = op0 + 8 * HW;   // row + 8
            *reinterpret_cast<float2*>(op0) = make_float2(acc[mi][ni][0], acc[mi][ni][1]);
            *reinterpret_cast<float2*>(op1) = make_float2(acc[mi][ni][2], acc[mi][ni][3]);
        }
    }
}

// ---------------- launcher ----------------
extern "C" void kernel_launch(void* const* d_in, const int* in_sizes, int n_in,
                              void* d_out, int out_size) {
    const float* x      = (const float*)d_in[0];
    const float* te     = (const float*)d_in[1];
    const float* weight = (const float*)d_in[2];
    const float* Wq = (const float*)d_in[3],  *bq = (const float*)d_in[4];
    const float* Wk = (const float*)d_in[5],  *bk = (const float*)d_in[6];
    const float* Wv = (const float*)d_in[7],  *bv = (const float*)d_in[8];
    const float* Wm1 = (const float*)d_in[9],  *bm1 = (const float*)d_in[10];
    const float* Wm2 = (const float*)d_in[11], *bm2 = (const float*)d_in[12];
    const float* Wc  = (const float*)d_in[13], *bc  = (const float*)d_in[14];
    float* out = (float*)d_out;

    cudaFuncSetAttribute(conv_kernel, cudaFuncAttributeMaxDynamicSharedMemorySize,
                         CONV_SMEM);

    pool_convert_kernel<<<(B_ * CIN) / 8, 256>>>(x);
    router_kernel<<<B_, HID>>>(te, Wq, bq, Wk, bk, Wv, bv, Wm1, bm1, Wm2, bm2, Wc, bc);
    mix_kernel<<<COUT, 256>>>(weight);
    conv_kernel<<<dim3(8, 2, B_), 256, CONV_SMEM>>>(out);
}

// round 5
// speedup vs baseline: 1.6189x; 1.0070x over previous
#include <cuda_runtime.h>
#include <cuda_fp16.h>
#include <cstdint>

// ---------------- problem dims ----------------
constexpr int B_   = 32;
constexpr int CIN  = 256;
constexpr int COUT = 256;
constexpr int HW   = 1024;   // 32x32
constexpr int TDIM = 256;
constexpr int HID  = 64;
constexpr int E_   = 4;
constexpr int TAPS = 9;

// ---------------- device scratch (static: allocation rules) ----------------
__device__ __align__(16) __half g_xh[(size_t)B_ * CIN * HW];              // x in fp16
__device__ float  g_pooled[B_ * CIN];
__device__ float  g_rw[B_ * E_];
__device__ __align__(16) __half g_weff[(size_t)B_ * TAPS * COUT * CIN];   // [b][tap][cout][cin]

// ---------------- helpers ----------------
#define SW128(off)  ((off) ^ (((off) >> 3) & 0x70))   // 128B-row swizzle

__device__ __forceinline__ uint32_t smem_u32(const void* p) {
    uint32_t a;
    asm("{ .reg .u64 t; cvta.to.shared.u64 t, %1; cvt.u32.u64 %0, t; }"
        : "=r"(a) : "l"(p));
    return a;
}
__device__ __forceinline__ void ldsm_x4(uint32_t* r, uint32_t addr) {
    asm volatile("ldmatrix.sync.aligned.m8n8.x4.shared.b16 {%0,%1,%2,%3}, [%4];"
                 : "=r"(r[0]), "=r"(r[1]), "=r"(r[2]), "=r"(r[3]) : "r"(addr));
}
__device__ __forceinline__ void mma16816(float* c, const uint32_t* a,
                                         uint32_t b0, uint32_t b1) {
    asm volatile(
        "mma.sync.aligned.m16n8k16.row.col.f32.f16.f16.f32 "
        "{%0,%1,%2,%3}, {%4,%5,%6,%7}, {%8,%9}, {%0,%1,%2,%3};"
        : "+f"(c[0]), "+f"(c[1]), "+f"(c[2]), "+f"(c[3])
        : "r"(a[0]), "r"(a[1]), "r"(a[2]), "r"(a[3]), "r"(b0), "r"(b1));
}
__device__ __forceinline__ void cp_async16(uint32_t dst, const void* src) {
    asm volatile("cp.async.cg.shared.global [%0], [%1], 16;" :: "r"(dst), "l"(src));
}
#define CP_COMMIT() asm volatile("cp.async.commit_group;" ::: "memory")
#define CP_WAIT(N)  asm volatile("cp.async.wait_group %0;" :: "n"(N) : "memory")

// ---------------- kernel 1: pool (mean over HW) + fp32->fp16 convert ----------------
__global__ __launch_bounds__(256) void pool_convert_kernel(const float* __restrict__ x) {
    int wid = threadIdx.x >> 5, lid = threadIdx.x & 31;
    int rc = blockIdx.x * 8 + wid;               // 0 .. B_*CIN-1
    const float4* xp = reinterpret_cast<const float4*>(x + (size_t)rc * HW);
    uint2* op = reinterpret_cast<uint2*>(g_xh + (size_t)rc * HW);
    float s = 0.f;
    #pragma unroll
    for (int i = 0; i < 8; i++) {
        float4 v = xp[lid + i * 32];
        s += (v.x + v.y) + (v.z + v.w);
        __half2 h0 = __floats2half2_rn(v.x, v.y);
        __half2 h1 = __floats2half2_rn(v.z, v.w);
        uint2 u;
        u.x = *reinterpret_cast<uint32_t*>(&h0);
        u.y = *reinterpret_cast<uint32_t*>(&h1);
        op[lid + i * 32] = u;
    }
    #pragma unroll
    for (int o = 16; o > 0; o >>= 1) s += __shfl_xor_sync(0xFFFFFFFFu, s, o);
    if (lid == 0) g_pooled[rc] = s * (1.f / 1024.f);
}

// ---------------- kernel 2: router MLP + softmax -> g_rw ----------------
__global__ __launch_bounds__(HID) void router_kernel(
    const float* __restrict__ te,
    const float* __restrict__ Wq, const float* __restrict__ bq,
    const float* __restrict__ Wk, const float* __restrict__ bk,
    const float* __restrict__ Wv, const float* __restrict__ bv,
    const float* __restrict__ Wm1, const float* __restrict__ bm1,
    const float* __restrict__ Wm2, const float* __restrict__ bm2,
    const float* __restrict__ Wc, const float* __restrict__ bc) {
    int b = blockIdx.x, j = threadIdx.x;
    __shared__ float s_in[TDIM], s_p[CIN], s_xa[HID], s_h[HID], s_xm[HID], s_l[E_];
    for (int i = j; i < TDIM; i += HID) s_in[i] = te[b * TDIM + i];
    for (int i = j; i < CIN; i += HID) s_p[i] = g_pooled[b * CIN + i];
    __syncthreads();

    float q = bq[j], k = bk[j], v = bv[j];
    for (int i = 0; i < TDIM; i++) q += Wq[j * TDIM + i] * s_in[i];
    for (int i = 0; i < CIN; i++) {
        float p = s_p[i];
        k += Wk[j * CIN + i] * p;
        v += Wv[j * CIN + i] * p;
    }
    float attn = 1.f / (1.f + expf(-(q * k)));
    float xa = v * attn;
    s_xa[j] = xa;
    __syncthreads();

    float h = bm1[j];
    for (int i = 0; i < HID; i++) h += Wm1[j * HID + i] * s_xa[i];
    h = h / (1.f + expf(-h));         // silu
    s_h[j] = h;
    __syncthreads();

    float xm = xa + bm2[j];
    for (int i = 0; i < HID; i++) xm += Wm2[j * HID + i] * s_h[i];
    s_xm[j] = xm;
    __syncthreads();

    if (j < E_) {
        float l = bc[j];
        for (int i = 0; i < HID; i++) l += Wc[j * HID + i] * s_xm[i];
        s_l[j] = l;
    }
    __syncthreads();
    if (j == 0) {
        float mx = s_l[0];
        for (int e = 1; e < E_; e++) mx = fmaxf(mx, s_l[e]);
        float sm = 0.f, ex[E_];
        for (int e = 0; e < E_; e++) { ex[e] = expf(s_l[e] - mx); sm += ex[e]; }
        float inv = 1.f / sm;
        for (int e = 0; e < E_; e++) g_rw[b * E_ + e] = ex[e] * inv;
    }
}

// ---------------- kernel 3: mix expert weights -> g_weff [b][tap][cout][cin] fp16 ----------------
__global__ __launch_bounds__(256) void mix_kernel(const float* __restrict__ weight) {
    int o = blockIdx.x, c = threadIdx.x;
    __shared__ float ws[E_ * CIN * TAPS];   // 36 KB: weight[:, o, :, :]
    __shared__ float srw[B_ * E_];
    for (int e = 0; e < E_; e++) {
        const float* src = weight + (size_t)(e * COUT + o) * (CIN * TAPS);
        for (int i = c; i < CIN * TAPS; i += 256) ws[e * CIN * TAPS + i] = src[i];
    }
    for (int i = c; i < B_ * E_; i += 256) srw[i] = g_rw[i];
    __syncthreads();

    float wv[E_][TAPS];
    #pragma unroll
    for (int e = 0; e < E_; e++)
        #pragma unroll
        for (int t = 0; t < TAPS; t++) wv[e][t] = ws[e * CIN * TAPS + c * TAPS + t];

    for (int b = 0; b < B_; b++) {
        float r0 = srw[b * 4 + 0], r1 = srw[b * 4 + 1];
        float r2 = srw[b * 4 + 2], r3 = srw[b * 4 + 3];
        #pragma unroll
        for (int t = 0; t < TAPS; t++) {
            float v = r0 * wv[0][t] + r1 * wv[1][t] + r2 * wv[2][t] + r3 * wv[3][t];
            g_weff[(((size_t)b * TAPS + t) * COUT + o) * CIN + c] = __float2half_rn(v);
        }
    }
}

// ---------------- kernel 4: batched implicit-GEMM conv via mma.sync (HMMA) ----------------
// CTA: b = blockIdx.z, mt = blockIdx.y (128 couts), nt = blockIdx.x (128 pixels = 4 rows)
// cc-chunk outer (x neighborhood loaded ONCE per chunk, all 9 taps via shifted
// addressing), tap inner. A double-buffered via cp.async, ONE barrier per stage.
constexpr int PIXB = 144;                 // bytes per pixel in sX (64 cin + 8 pad halves)
constexpr int ROWB = 34 * PIXB;           // 4896 B per image row (halo cols 0 and 33)
constexpr int SA_OFF   = 30720;           // 1024-aligned (>= 6*ROWB = 29376)
constexpr int SA_BYTES = 128 * 128;       // 16 KB per A buffer
constexpr int CONV_SMEM = SA_OFF + 2 * SA_BYTES;   // 63488

__global__ __launch_bounds__(256, 2) void conv_kernel(float* __restrict__ out) {
    extern __shared__ char smem[];
    char* sx = smem;
    const uint32_t sxa = smem_u32(sx);
    const uint32_t saa[2] = { sxa + SA_OFF, sxa + SA_OFF + SA_BYTES };

    const int tid = threadIdx.x, lid = tid & 31, wid = tid >> 5;
    const int nt = blockIdx.x, mt = blockIdx.y, b = blockIdx.z;
    const int wm = wid & 3, wn = wid >> 2;
    const int h0 = nt * 4;

    const __half* __restrict__ xb = g_xh + (size_t)b * CIN * HW;
    const __half* __restrict__ wbase =
        g_weff + ((size_t)b * TAPS * COUT + (size_t)mt * 128) * CIN;

    float acc[2][8][4];
    #pragma unroll
    for (int mi = 0; mi < 2; mi++)
        #pragma unroll
        for (int ni = 0; ni < 8; ni++)
            #pragma unroll
            for (int q = 0; q < 4; q++) acc[mi][ni][q] = 0.f;

    // ---- per-thread ldmatrix row addresses for B fragments ----
    // instr g covers n-tiles 2g (regs r0,r1 = k0-7,k8-15) and 2g+1 (r2,r3).
    // thread groups of 8 supply rows: 0-7:(2g,k0) 8-15:(2g,k8) 16-23:(2g+1,k0) 24-31:(2g+1,k8)
    uint32_t bg[4];
    {
        int kh = (lid >> 3) & 1, nodd = lid >> 4, pr = lid & 7;
        #pragma unroll
        for (int g = 0; g < 4; g++) {
            int n = wn * 64 + (2 * g + nodd) * 8 + pr;
            int r = n >> 5, w = n & 31;
            bg[g] = sxa + (uint32_t)(((r + 1) * 34 + (w + 1)) * PIXB + kh * 16);
        }
    }

    // ---- prologue: zero halo columns (once) + prefetch A(0) ----
    if (tid < 96) {
        int rr = tid / 16, sub = tid % 16;
        int col = (sub >> 3) ? 33 : 0, kq = sub & 7;
        *reinterpret_cast<uint4*>(sx + rr * ROWB + col * PIXB + kq * 16) =
            make_uint4(0u, 0u, 0u, 0u);
    }
    {
        #pragma unroll
        for (int i = 0; i < 4; i++) {
            int idx = i * 256 + tid;
            int m = idx >> 3, j = idx & 7;
            cp_async16(saa[0] + SW128((uint32_t)(m * 128 + j * 16)), wbase + m * CIN + j * 8);
        }
        CP_COMMIT();
    }

    const int kfill = tid >> 2;              // cin within chunk for sX fill
    const int wg    = tid & 3;               // 8-pixel group within image row

    #pragma unroll 1
    for (int cc = 0; cc < 4; cc++) {
        #pragma unroll
        for (int tap = 0; tap < TAPS; tap++) {
            const int s = cc * TAPS + tap;
            CP_WAIT(0);                      // this thread's A(s) copies done
            __syncthreads();                 // A(s) + sX visible; prev readers done

            if (tap == 0) {
                // fill sX for this chunk (prev chunk's readers finished at barrier)
                #pragma unroll
                for (int rr = 0; rr < 6; rr++) {
                    int h = h0 + rr - 1;
                    uint4 v = make_uint4(0u, 0u, 0u, 0u);
                    if ((unsigned)h < 32u)
                        v = *reinterpret_cast<const uint4*>(
                            xb + (size_t)(cc * 64 + kfill) * HW + h * 32 + wg * 8);
                    const ushort* p = reinterpret_cast<const ushort*>(&v);
                    char* base = sx + rr * ROWB + (1 + wg * 8) * PIXB + kfill * 2;
                    #pragma unroll
                    for (int q = 0; q < 8; q++)
                        *reinterpret_cast<ushort*>(base + q * PIXB) = p[q];
                }
                __syncthreads();
            }

            // prefetch next A tile into the other buffer (safe: barrier above)
            if (s < 35) {
                const int ntap = (tap == 8) ? 0 : tap + 1;
                const int ncc  = (tap == 8) ? cc + 1 : cc;
                const __half* asrc = wbase + (size_t)ntap * COUT * CIN + ncc * 64;
                const uint32_t dst = saa[(s + 1) & 1];
                #pragma unroll
                for (int i = 0; i < 4; i++) {
                    int idx = i * 256 + tid;
                    int m = idx >> 3, j = idx & 7;
                    cp_async16(dst + SW128((uint32_t)(m * 128 + j * 16)),
                               asrc + m * CIN + j * 8);
                }
                CP_COMMIT();
            }

            const uint32_t sa = saa[s & 1];
            const int dh = tap / 3 - 1, dw = tap % 3 - 1;
            const int delta = (dh * 34 + dw) * PIXB;

            #pragma unroll
            for (int ks = 0; ks < 4; ks++) {
                uint32_t afr[2][4];
                #pragma unroll
                for (int mi = 0; mi < 2; mi++) {
                    int row = wm * 32 + mi * 16 + (lid & 15);
                    uint32_t off = (uint32_t)(row * 128 + ks * 32 + (lid >> 4) * 16);
                    ldsm_x4(afr[mi], sa + SW128(off));
                }
                uint32_t breg[4][4];
                const uint32_t dlt = (uint32_t)(delta + ks * 32);
                #pragma unroll
                for (int g = 0; g < 4; g++) ldsm_x4(breg[g], bg[g] + dlt);
                #pragma unroll
                for (int nb = 0; nb < 8; nb++) {
                    uint32_t b0 = breg[nb >> 1][(nb & 1) * 2];
                    uint32_t b1 = breg[nb >> 1][(nb & 1) * 2 + 1];
                    mma16816(acc[0][nb], afr[0], b0, b1);
                    mma16816(acc[1][nb], afr[1], b0, b1);
                }
            }
        }
    }

    // ---- epilogue: accum regs -> out ----
    #pragma unroll
    for (int mi = 0; mi < 2; mi++) {
        #pragma unroll
        for (int ni = 0; ni < 8; ni++) {
            int row = mt * 128 + wm * 32 + mi * 16 + (lid >> 2);
            int col = nt * 128 + wn * 64 + ni * 8 + (lid & 3) * 2;
            float* op0 = out + ((size_t)b * COUT + row) * HW + col;
            float* op1 = op0 + 8 * HW;   // row + 8
            *reinterpret_cast<float2*>(op0) = make_float2(acc[mi][ni][0], acc[mi][ni][1]);
            *reinterpret_cast<float2*>(op1) = make_float2(acc[mi][ni][2], acc[mi][ni][3]);
        }
    }
}

// ---------------- launcher ----------------
extern "C" void kernel_launch(void* const* d_in, const int* in_sizes, int n_in,
                              void* d_out, int out_size) {
    const float* x      = (const float*)d_in[0];
    const float* te     = (const float*)d_in[1];
    const float* weight = (const float*)d_in[2];
    const float* Wq = (const float*)d_in[3],  *bq = (const float*)d_in[4];
    const float* Wk = (const float*)d_in[5],  *bk = (const float*)d_in[6];
    const float* Wv = (const float*)d_in[7],  *bv = (const float*)d_in[8];
    const float* Wm1 = (const float*)d_in[9],  *bm1 = (const float*)d_in[10];
    const float* Wm2 = (const float*)d_in[11], *bm2 = (const float*)d_in[12];
    const float* Wc  = (const float*)d_in[13], *bc  = (const float*)d_in[14];
    float* out = (float*)d_out;

    cudaFuncSetAttribute(conv_kernel, cudaFuncAttributeMaxDynamicSharedMemorySize,
                         CONV_SMEM);

    pool_convert_kernel<<<(B_ * CIN) / 8, 256>>>(x);
    router_kernel<<<B_, HID>>>(te, Wq, bq, Wk, bk, Wv, bv, Wm1, bm1, Wm2, bm2, Wc, bc);
    mix_kernel<<<COUT, 256>>>(weight);
    conv_kernel<<<dim3(8, 2, B_), 256, CONV_SMEM>>>(out);
}

// round 6
// speedup vs baseline: 1.7178x; 1.0611x over previous
#include <cuda_runtime.h>
#include <cuda_fp16.h>
#include <cstdint>

// ---------------- problem dims ----------------
constexpr int B_   = 32;
constexpr int CIN  = 256;
constexpr int COUT = 256;
constexpr int HW   = 1024;   // 32x32
constexpr int TDIM = 256;
constexpr int HID  = 64;
constexpr int E_   = 4;
constexpr int TAPS = 9;

// ---------------- device scratch (static: allocation rules) ----------------
__device__ __align__(16) __half g_xh[(size_t)B_ * CIN * HW];              // x in fp16
__device__ float  g_pooled[B_ * CIN];
__device__ float  g_rw[B_ * E_];
__device__ __align__(16) __half g_weff[(size_t)B_ * TAPS * COUT * CIN];   // [b][tap][cout][cin]

// ---------------- helpers ----------------
#define SW128(off)  ((off) ^ (((off) >> 3) & 0x70))   // 128B-row swizzle

__device__ __forceinline__ uint32_t smem_u32(const void* p) {
    uint32_t a;
    asm("{ .reg .u64 t; cvta.to.shared.u64 t, %1; cvt.u32.u64 %0, t; }"
        : "=r"(a) : "l"(p));
    return a;
}
__device__ __forceinline__ void ldsm_x4(uint32_t* r, uint32_t addr) {
    asm volatile("ldmatrix.sync.aligned.m8n8.x4.shared.b16 {%0,%1,%2,%3}, [%4];"
                 : "=r"(r[0]), "=r"(r[1]), "=r"(r[2]), "=r"(r[3]) : "r"(addr));
}
__device__ __forceinline__ void mma16816(float* c, const uint32_t* a,
                                         uint32_t b0, uint32_t b1) {
    asm volatile(
        "mma.sync.aligned.m16n8k16.row.col.f32.f16.f16.f32 "
        "{%0,%1,%2,%3}, {%4,%5,%6,%7}, {%8,%9}, {%0,%1,%2,%3};"
        : "+f"(c[0]), "+f"(c[1]), "+f"(c[2]), "+f"(c[3])
        : "r"(a[0]), "r"(a[1]), "r"(a[2]), "r"(a[3]), "r"(b0), "r"(b1));
}
__device__ __forceinline__ void cp_async16(uint32_t dst, const void* src) {
    asm volatile("cp.async.cg.shared.global [%0], [%1], 16;" :: "r"(dst), "l"(src));
}
#define CP_COMMIT() asm volatile("cp.async.commit_group;" ::: "memory")
#define CP_WAIT(N)  asm volatile("cp.async.wait_group %0;" :: "n"(N) : "memory")

// ---------------- kernel 1: pool (mean over HW) + fp32->fp16 convert ----------------
__global__ __launch_bounds__(256) void pool_convert_kernel(const float* __restrict__ x) {
    int wid = threadIdx.x >> 5, lid = threadIdx.x & 31;
    int rc = blockIdx.x * 8 + wid;               // 0 .. B_*CIN-1
    const float4* xp = reinterpret_cast<const float4*>(x + (size_t)rc * HW);
    uint2* op = reinterpret_cast<uint2*>(g_xh + (size_t)rc * HW);
    float s = 0.f;
    #pragma unroll
    for (int i = 0; i < 8; i++) {
        float4 v = xp[lid + i * 32];
        s += (v.x + v.y) + (v.z + v.w);
        __half2 h0 = __floats2half2_rn(v.x, v.y);
        __half2 h1 = __floats2half2_rn(v.z, v.w);
        uint2 u;
        u.x = *reinterpret_cast<uint32_t*>(&h0);
        u.y = *reinterpret_cast<uint32_t*>(&h1);
        op[lid + i * 32] = u;
    }
    #pragma unroll
    for (int o = 16; o > 0; o >>= 1) s += __shfl_xor_sync(0xFFFFFFFFu, s, o);
    if (lid == 0) g_pooled[rc] = s * (1.f / 1024.f);
}

// ---------------- kernel 2: router MLP + softmax -> g_rw ----------------
__global__ __launch_bounds__(HID) void router_kernel(
    const float* __restrict__ te,
    const float* __restrict__ Wq, const float* __restrict__ bq,
    const float* __restrict__ Wk, const float* __restrict__ bk,
    const float* __restrict__ Wv, const float* __restrict__ bv,
    const float* __restrict__ Wm1, const float* __restrict__ bm1,
    const float* __restrict__ Wm2, const float* __restrict__ bm2,
    const float* __restrict__ Wc, const float* __restrict__ bc) {
    int b = blockIdx.x, j = threadIdx.x;
    __shared__ float s_in[TDIM], s_p[CIN], s_xa[HID], s_h[HID], s_xm[HID], s_l[E_];
    for (int i = j; i < TDIM; i += HID) s_in[i] = te[b * TDIM + i];
    for (int i = j; i < CIN; i += HID) s_p[i] = g_pooled[b * CIN + i];
    __syncthreads();

    float q = bq[j], k = bk[j], v = bv[j];
    for (int i = 0; i < TDIM; i++) q += Wq[j * TDIM + i] * s_in[i];
    for (int i = 0; i < CIN; i++) {
        float p = s_p[i];
        k += Wk[j * CIN + i] * p;
        v += Wv[j * CIN + i] * p;
    }
    float attn = 1.f / (1.f + expf(-(q * k)));
    float xa = v * attn;
    s_xa[j] = xa;
    __syncthreads();

    float h = bm1[j];
    for (int i = 0; i < HID; i++) h += Wm1[j * HID + i] * s_xa[i];
    h = h / (1.f + expf(-h));         // silu
    s_h[j] = h;
    __syncthreads();

    float xm = xa + bm2[j];
    for (int i = 0; i < HID; i++) xm += Wm2[j * HID + i] * s_h[i];
    s_xm[j] = xm;
    __syncthreads();

    if (j < E_) {
        float l = bc[j];
        for (int i = 0; i < HID; i++) l += Wc[j * HID + i] * s_xm[i];
        s_l[j] = l;
    }
    __syncthreads();
    if (j == 0) {
        float mx = s_l[0];
        for (int e = 1; e < E_; e++) mx = fmaxf(mx, s_l[e]);
        float sm = 0.f, ex[E_];
        for (int e = 0; e < E_; e++) { ex[e] = expf(s_l[e] - mx); sm += ex[e]; }
        float inv = 1.f / sm;
        for (int e = 0; e < E_; e++) g_rw[b * E_ + e] = ex[e] * inv;
    }
}

// ---------------- kernel 3: mix expert weights -> g_weff [b][tap][cout][cin] fp16 ----------------
__global__ __launch_bounds__(256) void mix_kernel(const float* __restrict__ weight) {
    int o = blockIdx.x, c = threadIdx.x;
    __shared__ float ws[E_ * CIN * TAPS];   // 36 KB: weight[:, o, :, :]
    __shared__ float srw[B_ * E_];
    for (int e = 0; e < E_; e++) {
        const float* src = weight + (size_t)(e * COUT + o) * (CIN * TAPS);
        for (int i = c; i < CIN * TAPS; i += 256) ws[e * CIN * TAPS + i] = src[i];
    }
    for (int i = c; i < B_ * E_; i += 256) srw[i] = g_rw[i];
    __syncthreads();

    float wv[E_][TAPS];
    #pragma unroll
    for (int e = 0; e < E_; e++)
        #pragma unroll
        for (int t = 0; t < TAPS; t++) wv[e][t] = ws[e * CIN * TAPS + c * TAPS + t];

    for (int b = 0; b < B_; b++) {
        float r0 = srw[b * 4 + 0], r1 = srw[b * 4 + 1];
        float r2 = srw[b * 4 + 2], r3 = srw[b * 4 + 3];
        #pragma unroll
        for (int t = 0; t < TAPS; t++) {
            float v = r0 * wv[0][t] + r1 * wv[1][t] + r2 * wv[2][t] + r3 * wv[3][t];
            g_weff[(((size_t)b * TAPS + t) * COUT + o) * CIN + c] = __float2half_rn(v);
        }
    }
}

// ---------------- kernel 4: batched implicit-GEMM conv via mma.sync (HMMA) ----------------
// CTA: b = blockIdx.z, mt = blockIdx.y (128 couts), nt = blockIdx.x (128 pixels = 4 rows)
// 128 threads = 4 warps, warp tile 64(m) x 64(n)  ->  1.0 shared-wavefront per HMMA.
// cc-chunk outer (x neighborhood loaded ONCE per chunk, all 9 taps via shifted
// addressing), tap inner. A triple-buffered via cp.async (wait_group 1).
constexpr int PIXB = 144;                 // bytes per pixel in sX (64 cin + 8 pad halves)
constexpr int ROWB = 34 * PIXB;           // 4896 B per image row (halo cols 0 and 33)
constexpr int SA_OFF   = 30720;           // 1024-aligned (>= 6*ROWB = 29376)
constexpr int SA_BYTES = 128 * 128;       // 16 KB per A buffer
constexpr int CONV_SMEM = SA_OFF + 3 * SA_BYTES;   // 79872

__global__ __launch_bounds__(128, 2) void conv_kernel(float* __restrict__ out) {
    extern __shared__ char smem[];
    char* sx = smem;
    const uint32_t sxa = smem_u32(sx);
    const uint32_t saa[3] = { sxa + SA_OFF, sxa + SA_OFF + SA_BYTES,
                              sxa + SA_OFF + 2 * SA_BYTES };

    const int tid = threadIdx.x, lid = tid & 31, wid = tid >> 5;
    const int nt = blockIdx.x, mt = blockIdx.y, b = blockIdx.z;
    const int wm = wid & 1, wn = wid >> 1;
    const int h0 = nt * 4;

    const __half* __restrict__ xb = g_xh + (size_t)b * CIN * HW;
    const __half* __restrict__ wbase =
        g_weff + ((size_t)b * TAPS * COUT + (size_t)mt * 128) * CIN;

    float acc[4][8][4];
    #pragma unroll
    for (int mi = 0; mi < 4; mi++)
        #pragma unroll
        for (int ni = 0; ni < 8; ni++)
            #pragma unroll
            for (int q = 0; q < 4; q++) acc[mi][ni][q] = 0.f;

    // ---- per-thread ldmatrix row addresses for B fragments ----
    // instr g covers n-tiles 2g (regs r0,r1) and 2g+1 (r2,r3) within this warp's 64 n.
    uint32_t bg[4];
    {
        int kh = (lid >> 3) & 1, nodd = lid >> 4, pr = lid & 7;
        #pragma unroll
        for (int g = 0; g < 4; g++) {
            int n = wn * 64 + (2 * g + nodd) * 8 + pr;
            int r = n >> 5, w = n & 31;
            bg[g] = sxa + (uint32_t)(((r + 1) * 34 + (w + 1)) * PIXB + kh * 16);
        }
    }

    // ---- prologue: zero halo columns (once) + prefetch A(0), A(1) ----
    if (tid < 96) {
        int rr = tid / 16, sub = tid % 16;
        int col = (sub >> 3) ? 33 : 0, kq = sub & 7;
        *reinterpret_cast<uint4*>(sx + rr * ROWB + col * PIXB + kq * 16) =
            make_uint4(0u, 0u, 0u, 0u);
    }
    #pragma unroll
    for (int p = 0; p < 2; p++) {
        const __half* asrc = wbase + (size_t)p * COUT * CIN;   // taps 0 and 1, cc 0
        #pragma unroll
        for (int i = 0; i < 8; i++) {
            int idx = i * 128 + tid;
            int m = idx >> 3, j = idx & 7;
            cp_async16(saa[p] + SW128((uint32_t)(m * 128 + j * 16)), asrc + m * CIN + j * 8);
        }
        CP_COMMIT();
    }

    #pragma unroll 1
    for (int cc = 0; cc < 4; cc++) {
        #pragma unroll
        for (int tap = 0; tap < TAPS; tap++) {
            const bool lastS = (cc == 3) && (tap == 8);
            if (lastS) { CP_WAIT(0); } else { CP_WAIT(1); }   // A(s) resident
            __syncthreads();                 // A(s)+sX visible; stage s-1 readers done

            if (tap == 0) {
                // fill sX for this chunk (prev chunk's readers finished at barrier)
                #pragma unroll
                for (int q2 = 0; q2 < 2; q2++) {
                    int idx = q2 * 128 + tid;
                    int kfill = idx >> 2, wg = idx & 3;
                    #pragma unroll
                    for (int rr = 0; rr < 6; rr++) {
                        int h = h0 + rr - 1;
                        uint4 v = make_uint4(0u, 0u, 0u, 0u);
                        if ((unsigned)h < 32u)
                            v = *reinterpret_cast<const uint4*>(
                                xb + (size_t)(cc * 64 + kfill) * HW + h * 32 + wg * 8);
                        const ushort* p = reinterpret_cast<const ushort*>(&v);
                        char* base = sx + rr * ROWB + (1 + wg * 8) * PIXB + kfill * 2;
                        #pragma unroll
                        for (int q = 0; q < 8; q++)
                            *reinterpret_cast<ushort*>(base + q * PIXB) = p[q];
                    }
                }
                __syncthreads();
            }

            // prefetch A(s+2) into buffer (tap+2)%3  (9 % 3 == 0 so cc drops out)
            if (!((cc == 3) && (tap >= 7))) {
                const int ntap = (tap + 2 < TAPS) ? tap + 2 : tap + 2 - TAPS;
                const int ncc  = (tap + 2 < TAPS) ? cc : cc + 1;
                const __half* asrc = wbase + (size_t)ntap * COUT * CIN + ncc * 64;
                const uint32_t dst = saa[(tap + 2) % 3];
                #pragma unroll
                for (int i = 0; i < 8; i++) {
                    int idx = i * 128 + tid;
                    int m = idx >> 3, j = idx & 7;
                    cp_async16(dst + SW128((uint32_t)(m * 128 + j * 16)),
                               asrc + m * CIN + j * 8);
                }
                CP_COMMIT();
            }

            const uint32_t sa = saa[tap % 3];
            const int dh = tap / 3 - 1, dw = tap % 3 - 1;
            const int delta = (dh * 34 + dw) * PIXB;

            #pragma unroll
            for (int ks = 0; ks < 4; ks++) {
                uint32_t afr[4][4];
                #pragma unroll
                for (int mi = 0; mi < 4; mi++) {
                    int row = wm * 64 + mi * 16 + (lid & 15);
                    uint32_t off = (uint32_t)(row * 128 + ks * 32 + (lid >> 4) * 16);
                    ldsm_x4(afr[mi], sa + SW128(off));
                }
                uint32_t breg[4][4];
                const uint32_t dlt = (uint32_t)(delta + ks * 32);
                #pragma unroll
                for (int g = 0; g < 4; g++) ldsm_x4(breg[g], bg[g] + dlt);
                #pragma unroll
                for (int mi = 0; mi < 4; mi++)
                    #pragma unroll
                    for (int nb = 0; nb < 8; nb++) {
                        uint32_t b0 = breg[nb >> 1][(nb & 1) * 2];
                        uint32_t b1 = breg[nb >> 1][(nb & 1) * 2 + 1];
                        mma16816(acc[mi][nb], afr[mi], b0, b1);
                    }
            }
        }
    }

    // ---- epilogue: accum regs -> out ----
    #pragma unroll
    for (int mi = 0; mi < 4; mi++) {
        #pragma unroll
        for (int ni = 0; ni < 8; ni++) {
            int row = mt * 128 + wm * 64 + mi * 16 + (lid >> 2);
            int col = nt * 128 + wn * 64 + ni * 8 + (lid & 3) * 2;
            float* op0 = out + ((size_t)b * COUT + row) * HW + col;
            float* op1 = op0 + 8 * HW;   // row + 8
            *reinterpret_cast<float2*>(op0) = make_float2(acc[mi][ni][0], acc[mi][ni][1]);
            *reinterpret_cast<float2*>(op1) = make_float2(acc[mi][ni][2], acc[mi][ni][3]);
        }
    }
}

// ---------------- launcher ----------------
extern "C" void kernel_launch(void* const* d_in, const int* in_sizes, int n_in,
                              void* d_out, int out_size) {
    const float* x      = (const float*)d_in[0];
    const float* te     = (const float*)d_in[1];
    const float* weight = (const float*)d_in[2];
    const float* Wq = (const float*)d_in[3],  *bq = (const float*)d_in[4];
    const float* Wk = (const float*)d_in[5],  *bk = (const float*)d_in[6];
    const float* Wv = (const float*)d_in[7],  *bv = (const float*)d_in[8];
    const float* Wm1 = (const float*)d_in[9],  *bm1 = (const float*)d_in[10];
    const float* Wm2 = (const float*)d_in[11], *bm2 = (const float*)d_in[12];
    const float* Wc  = (const float*)d_in[13], *bc  = (const float*)d_in[14];
    float* out = (float*)d_out;

    cudaFuncSetAttribute(conv_kernel, cudaFuncAttributeMaxDynamicSharedMemorySize,
                         CONV_SMEM);

    pool_convert_kernel<<<(B_ * CIN) / 8, 256>>>(x);
    router_kernel<<<B_, HID>>>(te, Wq, bq, Wk, bk, Wv, bv, Wm1, bm1, Wm2, bm2, Wc, bc);
    mix_kernel<<<COUT, 256>>>(weight);
    conv_kernel<<<dim3(8, 2, B_), 128, CONV_SMEM>>>(out);
}